// round 15
// baseline (speedup 1.0000x reference)
#include <cuda_runtime.h>
#include <cuda_fp16.h>

#define TABLE_N 2048
#define XMIN    (-6.0f)
#define XRANGE  (12.0f)
#define MAGIC_C (5.0f)

// Table cell i packs (y0, y1-y0) as half2 -> 4B LDS gather.
__device__ __half2 g_table[TABLE_N];   // 8 KB

// Kernel 1: build the LUT for g(x) = sum_k a_k * tanh(C*(x + b_k)).
__global__ void build_table_kernel(const float* __restrict__ w, int m1) {
    int i = blockIdx.x * blockDim.x + threadIdx.x;
    if (i >= TABLE_N) return;
    const float h = XRANGE / (float)TABLE_N;
    float x0 = XMIN + (float)i * h;
    float x1 = x0 + h;
    float y0 = 0.0f, y1 = 0.0f;
    for (int k = 0; k < m1; ++k) {
        float a = w[2 * k];
        float b = w[2 * k + 1];
        y0 += a * tanhf(MAGIC_C * (x0 + b));
        y1 += a * tanhf(MAGIC_C * (x1 + b));
    }
    // Round y0 to half first; dy relative to the ROUNDED y0 so the f->1
    // endpoint self-corrects y0's quantization error.
    __half h0 = __float2half_rn(y0);
    float  y0r = __half2float(h0);
    __half hd = __float2half_rn(y1 - y0r);
    g_table[i] = __halves2half2(h0, hd);
}

__device__ __forceinline__ float eval_lut(float xv, const __half2* __restrict__ tab,
                                          float inv_h, float off) {
    float t = fmaf(xv, inv_h, off);                    // (xv - XMIN) * inv_h
    t = fminf(fmaxf(t, 0.0f), (float)TABLE_N - 0.5f);  // clamp; g flat outside
    int   idx = (int)t;
    float f   = t - (float)idx;
    float2 e  = __half22float2(tab[idx]);
    return fmaf(f, e.y, e.x);
}

__device__ __forceinline__ float4 eval4(float4 v, const __half2* __restrict__ tab,
                                        float inv_h, float off) {
    float4 r;
    r.x = eval_lut(v.x, tab, inv_h, off);
    r.y = eval_lut(v.y, tab, inv_h, off);
    r.z = eval_lut(v.z, tab, inv_h, off);
    r.w = eval_lut(v.w, tab, inv_h, off);
    return r;
}

// Kernel 2: exact mapping — each thread handles exactly 4 float4, front-batched.
// Loads issued BEFORE __syncthreads so DRAM latency overlaps the table broadcast.
__global__ __launch_bounds__(256) void apply_lut_kernel(const float4* __restrict__ x,
                                                        float4* __restrict__ out,
                                                        int n4) {
    __shared__ __half2 s_tab[TABLE_N];  // 8 KB = 512 float4

    // Broadcast table: 2 float4 per thread (256 threads x 32 B = 8 KB).
    {
        float4* s4 = reinterpret_cast<float4*>(s_tab);
        const float4* g4 = reinterpret_cast<const float4*>(g_table);
        s4[threadIdx.x]       = g4[threadIdx.x];
        s4[threadIdx.x + 256] = g4[threadIdx.x + 256];
    }

    const int i0 = blockIdx.x * 1024 + threadIdx.x;  // 4 float4 per thread, stride 256
    const int i1 = i0 + 256;
    const int i2 = i0 + 512;
    const int i3 = i0 + 768;

    // Front-batch all global loads before the sync (independent of the table).
    float4 v0, v1, v2, v3;
    bool p0 = i0 < n4, p1 = i1 < n4, p2 = i2 < n4, p3 = i3 < n4;
    if (p0) v0 = __ldcs(&x[i0]);
    if (p1) v1 = __ldcs(&x[i1]);
    if (p2) v2 = __ldcs(&x[i2]);
    if (p3) v3 = __ldcs(&x[i3]);

    __syncthreads();

    const float inv_h = (float)TABLE_N / XRANGE;
    const float off   = -XMIN * inv_h;

    if (p0) { float4 r = eval4(v0, s_tab, inv_h, off); __stcs(&out[i0], r); }
    if (p1) { float4 r = eval4(v1, s_tab, inv_h, off); __stcs(&out[i1], r); }
    if (p2) { float4 r = eval4(v2, s_tab, inv_h, off); __stcs(&out[i2], r); }
    if (p3) { float4 r = eval4(v3, s_tab, inv_h, off); __stcs(&out[i3], r); }
}

extern "C" void kernel_launch(void* const* d_in, const int* in_sizes, int n_in,
                              void* d_out, int out_size) {
    const float* x = (const float*)d_in[0];
    const float* w = (const float*)d_in[1];
    float* out = (float*)d_out;

    int m1 = in_sizes[1] / 2;        // number of (a,b) pairs = M-1 = 7
    int n  = in_sizes[0];            // 8388608
    int n4 = n / 4;                  // 2097152 = 2^21

    build_table_kernel<<<(TABLE_N + 127) / 128, 128>>>(w, m1);
    int grid = (n4 + 1023) / 1024;   // 2048: each CTA covers 1024 float4 exactly
    apply_lut_kernel<<<grid, 256>>>((const float4*)x, (float4*)out, n4);
}

// round 16
// speedup vs baseline: 1.0723x; 1.0723x over previous
#include <cuda_runtime.h>
#include <cuda_fp16.h>

#define TABLE_N 2048
#define XMIN    (-6.0f)
#define XRANGE  (12.0f)
#define MAGIC_C (5.0f)

// Table cell i packs (y0, y1-y0) as half2 -> 4B LDS gather.
__device__ __half2 g_table[TABLE_N];   // 8 KB

// Kernel 1: build the LUT for g(x) = sum_k a_k * tanh(C*(x + b_k)).
__global__ void build_table_kernel(const float* __restrict__ w, int m1) {
    int i = blockIdx.x * blockDim.x + threadIdx.x;
    if (i >= TABLE_N) return;
    const float h = XRANGE / (float)TABLE_N;
    float x0 = XMIN + (float)i * h;
    float x1 = x0 + h;
    float y0 = 0.0f, y1 = 0.0f;
    for (int k = 0; k < m1; ++k) {
        float a = w[2 * k];
        float b = w[2 * k + 1];
        y0 += a * tanhf(MAGIC_C * (x0 + b));
        y1 += a * tanhf(MAGIC_C * (x1 + b));
    }
    // Round y0 to half first; dy relative to the ROUNDED y0 so the f->1
    // endpoint self-corrects y0's quantization error.
    __half h0 = __float2half_rn(y0);
    float  y0r = __half2float(h0);
    __half hd = __float2half_rn(y1 - y0r);
    g_table[i] = __halves2half2(h0, hd);
}

__device__ __forceinline__ float eval_lut(float xv, const __half2* __restrict__ tab,
                                          float inv_h, float off) {
    float t = fmaf(xv, inv_h, off);                    // (xv - XMIN) * inv_h
    t = fminf(fmaxf(t, 0.0f), (float)TABLE_N - 0.5f);  // clamp; g flat outside
    int   idx = (int)t;
    float f   = t - (float)idx;
    float2 e  = __half22float2(tab[idx]);
    return fmaf(f, e.y, e.x);
}

__device__ __forceinline__ float4 eval4(float4 v, const __half2* __restrict__ tab,
                                        float inv_h, float off) {
    float4 r;
    r.x = eval_lut(v.x, tab, inv_h, off);
    r.y = eval_lut(v.y, tab, inv_h, off);
    r.z = eval_lut(v.z, tab, inv_h, off);
    r.w = eval_lut(v.w, tab, inv_h, off);
    return r;
}

// Kernel 2: exact mapping — each thread handles exactly 4 float4, front-batched.
// Loads issued BEFORE __syncthreads so DRAM latency overlaps the table broadcast.
__global__ __launch_bounds__(256) void apply_lut_kernel(const float4* __restrict__ x,
                                                        float4* __restrict__ out,
                                                        int n4) {
    __shared__ __half2 s_tab[TABLE_N];  // 8 KB = 512 float4

    // Broadcast table: 2 float4 per thread (256 threads x 32 B = 8 KB).
    {
        float4* s4 = reinterpret_cast<float4*>(s_tab);
        const float4* g4 = reinterpret_cast<const float4*>(g_table);
        s4[threadIdx.x]       = g4[threadIdx.x];
        s4[threadIdx.x + 256] = g4[threadIdx.x + 256];
    }

    const int i0 = blockIdx.x * 1024 + threadIdx.x;  // 4 float4 per thread, stride 256
    const int i1 = i0 + 256;
    const int i2 = i0 + 512;
    const int i3 = i0 + 768;

    // Front-batch all global loads before the sync (independent of the table).
    float4 v0, v1, v2, v3;
    bool p0 = i0 < n4, p1 = i1 < n4, p2 = i2 < n4, p3 = i3 < n4;
    if (p0) v0 = __ldcs(&x[i0]);
    if (p1) v1 = __ldcs(&x[i1]);
    if (p2) v2 = __ldcs(&x[i2]);
    if (p3) v3 = __ldcs(&x[i3]);

    __syncthreads();

    const float inv_h = (float)TABLE_N / XRANGE;
    const float off   = -XMIN * inv_h;

    if (p0) { float4 r = eval4(v0, s_tab, inv_h, off); __stcs(&out[i0], r); }
    if (p1) { float4 r = eval4(v1, s_tab, inv_h, off); __stcs(&out[i1], r); }
    if (p2) { float4 r = eval4(v2, s_tab, inv_h, off); __stcs(&out[i2], r); }
    if (p3) { float4 r = eval4(v3, s_tab, inv_h, off); __stcs(&out[i3], r); }
}

extern "C" void kernel_launch(void* const* d_in, const int* in_sizes, int n_in,
                              void* d_out, int out_size) {
    const float* x = (const float*)d_in[0];
    const float* w = (const float*)d_in[1];
    float* out = (float*)d_out;

    int m1 = in_sizes[1] / 2;        // number of (a,b) pairs = M-1 = 7
    int n  = in_sizes[0];            // 8388608
    int n4 = n / 4;                  // 2097152 = 2^21

    build_table_kernel<<<(TABLE_N + 127) / 128, 128>>>(w, m1);
    int grid = (n4 + 1023) / 1024;   // 2048: each CTA covers 1024 float4 exactly
    apply_lut_kernel<<<grid, 256>>>((const float4*)x, (float4*)out, n4);
}